// round 14
// baseline (speedup 1.0000x reference)
#include <cuda_runtime.h>
#include <cuda_bf16.h>
#include <math.h>
#include <cstdint>

// Problem constants
#define BATCH 2
#define TSEQ  2048
#define CDIM  1024
#define NH    16
#define HD    64
#define M_ROWS (BATCH*TSEQ)      // 4096
#define N_QKV  (3*CDIM)          // 3072
#define QKVSZ  (BATCH*NH*TSEQ*HD)

// ---------------------------------------------------------------------------
// Global scratch: everything pre-split into bf16 hi/lo (no cudaMalloc allowed)
// ---------------------------------------------------------------------------
__device__ __nv_bfloat16 g_Xh[M_ROWS*CDIM],  g_Xl[M_ROWS*CDIM];
__device__ __nv_bfloat16 g_Wih[N_QKV*CDIM],  g_Wil[N_QKV*CDIM];
__device__ __nv_bfloat16 g_Woh[CDIM*CDIM],   g_Wol[CDIM*CDIM];
__device__ __nv_bfloat16 g_Qh[QKVSZ], g_Ql[QKVSZ];
__device__ __nv_bfloat16 g_Kh[QKVSZ], g_Kl[QKVSZ];
__device__ __nv_bfloat16 g_Vh[QKVSZ], g_Vl[QKVSZ];
__device__ __nv_bfloat16 g_AOh[M_ROWS*CDIM], g_AOl[M_ROWS*CDIM];

// ---------------------------------------------------------------------------
// Helpers
// ---------------------------------------------------------------------------
__device__ __forceinline__ void mma_bf16(float* c, const uint32_t* a, const uint32_t* b) {
    asm volatile(
        "mma.sync.aligned.m16n8k16.row.col.f32.bf16.bf16.f32 "
        "{%0,%1,%2,%3}, {%4,%5,%6,%7}, {%8,%9}, {%0,%1,%2,%3};"
        : "+f"(c[0]), "+f"(c[1]), "+f"(c[2]), "+f"(c[3])
        : "r"(a[0]), "r"(a[1]), "r"(a[2]), "r"(a[3]), "r"(b[0]), "r"(b[1]));
}

__device__ __forceinline__ void ldsm_x4(uint32_t* r, uint32_t saddr) {
    asm volatile("ldmatrix.sync.aligned.m8n8.x4.shared.b16 {%0,%1,%2,%3}, [%4];"
        : "=r"(r[0]), "=r"(r[1]), "=r"(r[2]), "=r"(r[3]) : "r"(saddr));
}

__device__ __forceinline__ void cp_async16(uint32_t smem_dst, const void* gmem_src) {
    asm volatile("cp.async.cg.shared.global [%0], [%1], 16;" :: "r"(smem_dst), "l"(gmem_src));
}
__device__ __forceinline__ void cp_commit() { asm volatile("cp.async.commit_group;"); }
template<int N>
__device__ __forceinline__ void cp_wait() { asm volatile("cp.async.wait_group %0;" :: "n"(N)); }

__device__ __forceinline__ void split2(float x, float y, uint32_t& h, uint32_t& l) {
    __nv_bfloat16 hx = __float2bfloat16(x);
    __nv_bfloat16 hy = __float2bfloat16(y);
    float rx = x - __bfloat162float(hx);
    float ry = y - __bfloat162float(hy);
    __nv_bfloat162 hp = __halves2bfloat162(hx, hy);
    __nv_bfloat162 lp = __floats2bfloat162_rn(rx, ry);
    h = *reinterpret_cast<uint32_t*>(&hp);
    l = *reinterpret_cast<uint32_t*>(&lp);
}
__device__ __forceinline__ void split1(float x, __nv_bfloat16& h, __nv_bfloat16& l) {
    h = __float2bfloat16(x);
    l = __float2bfloat16(x - __bfloat162float(h));
}

// fast exp for x <= 0, FMA pipe only
__device__ __forceinline__ float fast_exp(float x) {
    x = fmaxf(x, -87.0f);
    const float LOG2E = 1.4426950408889634f;
    float t  = fmaf(x, LOG2E, 12582912.0f);
    int   ni = __float_as_int(t) - 0x4B400000;
    float f  = fmaf(x, LOG2E, -(t - 12582912.0f));
    float p = 0.0013333558146428443f;
    p = fmaf(p, f, 0.009618129107628477f);
    p = fmaf(p, f, 0.05550410866482158f);
    p = fmaf(p, f, 0.2402265069591007f);
    p = fmaf(p, f, 0.6931471805599453f);
    p = fmaf(p, f, 1.0f);
    return p * __int_as_float((ni + 127) << 23);
}

// ---------------------------------------------------------------------------
// fp32 -> bf16 hi/lo split kernel (vectorized, memory bound)
// ---------------------------------------------------------------------------
__global__ __launch_bounds__(256)
void split_kernel(const float* __restrict__ src, __nv_bfloat16* __restrict__ h,
                  __nv_bfloat16* __restrict__ l, int n4)
{
    int i = blockIdx.x * 256 + threadIdx.x;
    if (i < n4) {
        float4 v = reinterpret_cast<const float4*>(src)[i];
        uint2 hh, ll;
        split2(v.x, v.y, hh.x, ll.x);
        split2(v.z, v.w, hh.y, ll.y);
        reinterpret_cast<uint2*>(h)[i] = hh;
        reinterpret_cast<uint2*>(l)[i] = ll;
    }
}

// ---------------------------------------------------------------------------
// bf16x3 GEMM on pre-split inputs: Out[m,n] = sum_k A[m,k]*W[n,k] + bias[n]
// BM=BN=128, BK=32 (bf16), 256 threads, cp.async double buffer, ldmatrix.
// EPI=0: scatter split Q/K/V (Q pre-scaled by 0.125); EPI=1: fp32 out.
// ---------------------------------------------------------------------------
#define GBK 32
#define GROWB 80                      // bytes per smem row (64 + 16 pad)
#define TILE_B (128*GROWB)            // 10240 bytes per tile
#define BUF_B  (4*TILE_B)             // Ah,Al,Bh,Bl
#define GSMEM  (2*BUF_B)              // 81920

template<int EPI>
__global__ __launch_bounds__(256, 2)
void gemm_split(const __nv_bfloat16* __restrict__ Ah, const __nv_bfloat16* __restrict__ Al,
                const __nv_bfloat16* __restrict__ Bh, const __nv_bfloat16* __restrict__ Bl,
                const float* __restrict__ bias, float* __restrict__ Out,
                int M, int N, int K)
{
    extern __shared__ char smem[];
    const uint32_t sbase = (uint32_t)__cvta_generic_to_shared(smem);

    const int tid  = threadIdx.x;
    const int wid  = tid >> 5;
    const int lane = tid & 31;
    const int g    = lane >> 2;
    const int q    = lane & 3;

    const int aRow0 = blockIdx.y * 128;
    const int nCol0 = blockIdx.x * 128;
    const int warpM = (wid >> 2) * 64;
    const int warpN = (wid & 3) * 32;

    float acc[4][4][4];
#pragma unroll
    for (int i = 0; i < 4; i++)
#pragma unroll
        for (int j = 0; j < 4; j++)
#pragma unroll
            for (int e = 0; e < 4; e++) acc[i][j][e] = 0.0f;

    const int NC = K / GBK;

    auto stage = [&](int c, int buf) {
        const int k0 = c * GBK;
        const uint32_t base = sbase + buf * BUF_B;
        // 512 16B-chunks per tile; 2 per thread per tile
#pragma unroll
        for (int it = 0; it < 2; it++) {
            const int idx = tid + it * 256;
            const int row = idx >> 2, seg = idx & 3;
            const uint32_t dst = base + row * GROWB + seg * 16;
            const size_t  ga  = (size_t)(aRow0 + row) * K + k0 + seg * 8;
            const size_t  gb  = (size_t)(nCol0 + row) * K + k0 + seg * 8;
            cp_async16(dst,              Ah + ga);
            cp_async16(dst + TILE_B,     Al + ga);
            cp_async16(dst + 2*TILE_B,   Bh + gb);
            cp_async16(dst + 3*TILE_B,   Bl + gb);
        }
        cp_commit();
    };

    stage(0, 0);

    // ldmatrix lane addressing: row = lane&15, k-half = lane>>4
    const int lrow  = lane & 15;
    const int lhalf = (lane >> 4) * 16;   // byte offset

    for (int c = 0; c < NC; c++) {
        const int buf = c & 1;
        if (c + 1 < NC) { stage(c + 1, buf ^ 1); cp_wait<1>(); }
        else            { cp_wait<0>(); }
        __syncthreads();

        const uint32_t base = sbase + buf * BUF_B;
#pragma unroll
        for (int ks = 0; ks < 2; ks++) {
            const uint32_t kofs = ks * 32 + lhalf;
            uint32_t ah[4][4], al[4][4], bh[2][4], bl[2][4];
#pragma unroll
            for (int i = 0; i < 4; i++) {
                const uint32_t ra = base + (warpM + i * 16 + lrow) * GROWB + kofs;
                ldsm_x4(ah[i], ra);
                ldsm_x4(al[i], ra + TILE_B);
            }
#pragma unroll
            for (int jp = 0; jp < 2; jp++) {
                const uint32_t rb = base + 2*TILE_B + (warpN + jp * 16 + lrow) * GROWB + kofs;
                ldsm_x4(bh[jp], rb);
                ldsm_x4(bl[jp], rb + TILE_B);
            }
#pragma unroll
            for (int i = 0; i < 4; i++)
#pragma unroll
                for (int j = 0; j < 4; j++) {
                    const int jp = j >> 1, sub = j & 1;
                    uint32_t bfh[2] = { bh[jp][sub], bh[jp][sub + 2] };
                    uint32_t bfl[2] = { bl[jp][sub], bl[jp][sub + 2] };
                    mma_bf16(acc[i][j], ah[i], bfh);
                    mma_bf16(acc[i][j], al[i], bfh);
                    mma_bf16(acc[i][j], ah[i], bfl);
                }
        }
        __syncthreads();
    }

    // ---------------- epilogue ----------------
#pragma unroll
    for (int i = 0; i < 4; i++) {
        const int mlo = aRow0 + warpM + i * 16 + g;
        const int mhi = mlo + 8;
#pragma unroll
        for (int j = 0; j < 4; j++) {
            const int n0 = nCol0 + warpN + j * 8 + 2 * q;
            const float b0 = __ldg(&bias[n0]);
            const float b1 = __ldg(&bias[n0 + 1]);
            float v00 = acc[i][j][0] + b0;
            float v01 = acc[i][j][1] + b1;
            float v10 = acc[i][j][2] + b0;
            float v11 = acc[i][j][3] + b1;
            if (EPI == 0) {
                // scatter split: n = d*48 + kk*16 + h ; kk: 0->Q(scaled), 1->V, 2->K
#pragma unroll
                for (int e = 0; e < 4; e++) {
                    const int n = n0 + (e & 1);
                    const int m = (e < 2) ? mlo : mhi;
                    float val = (e == 0) ? v00 : (e == 1) ? v01 : (e == 2) ? v10 : v11;
                    const int d   = n / 48;
                    const int rem = n - d * 48;
                    const int kk  = rem >> 4;
                    const int hh  = rem & 15;
                    const int bb  = m >> 11, t = m & 2047;
                    const int idx = (((bb * NH + hh) * TSEQ) + t) * HD + d;
                    __nv_bfloat16 hv, lv;
                    if (kk == 0) {
                        split1(val * 0.125f, hv, lv);       // fold 1/sqrt(D), exact
                        g_Qh[idx] = hv; g_Ql[idx] = lv;
                    } else if (kk == 1) {
                        split1(val, hv, lv);
                        g_Vh[idx] = hv; g_Vl[idx] = lv;
                    } else {
                        split1(val, hv, lv);
                        g_Kh[idx] = hv; g_Kl[idx] = lv;
                    }
                }
            } else {
                *reinterpret_cast<float2*>(&Out[(size_t)mlo * N + n0]) = make_float2(v00, v01);
                *reinterpret_cast<float2*>(&Out[(size_t)mhi * N + n0]) = make_float2(v10, v11);
            }
        }
    }
}

// ---------------------------------------------------------------------------
// Tensor-core causal flash attention on pre-split bf16 Q/K/V.
// 128 q-rows/CTA, 64-key blocks, 8 warps, 256 threads.
// Writes AO as split bf16 for the out-projection.
// ---------------------------------------------------------------------------
#define FKS 36            // uint32 stride per K smem row (64 bf16 + 8 pad)

__global__ __launch_bounds__(256)
void flash_tc()
{
    __shared__ uint32_t sKhi[64*FKS], sKlo[64*FKS];
    __shared__ __nv_bfloat16 sVthi[64*(2*FKS)], sVtlo[64*(2*FKS)];

    const int tid  = threadIdx.x;
    const int wid  = tid >> 5;
    const int lane = tid & 31;
    const int g    = lane >> 2;
    const int q    = lane & 3;

    const int bh   = blockIdx.y;
    const int row0 = blockIdx.x * 128;
    const int r0   = row0 + wid * 16 + g;
    const int r1   = r0 + 8;

    // Q fragments: direct bf16 hi/lo loads (pre-scaled by 1/8 in QKV epilogue)
    uint32_t qh[4][4], ql[4][4];
    {
        const uint32_t* Qh32 = reinterpret_cast<const uint32_t*>(g_Qh) + (size_t)bh * TSEQ * 32;
        const uint32_t* Ql32 = reinterpret_cast<const uint32_t*>(g_Ql) + (size_t)bh * TSEQ * 32;
#pragma unroll
        for (int kc = 0; kc < 4; kc++) {
            const int o0 = kc * 8 + q;
            qh[kc][0] = Qh32[(size_t)r0 * 32 + o0];
            qh[kc][1] = Qh32[(size_t)r1 * 32 + o0];
            qh[kc][2] = Qh32[(size_t)r0 * 32 + o0 + 4];
            qh[kc][3] = Qh32[(size_t)r1 * 32 + o0 + 4];
            ql[kc][0] = Ql32[(size_t)r0 * 32 + o0];
            ql[kc][1] = Ql32[(size_t)r1 * 32 + o0];
            ql[kc][2] = Ql32[(size_t)r0 * 32 + o0 + 4];
            ql[kc][3] = Ql32[(size_t)r1 * 32 + o0 + 4];
        }
    }

    float o[8][4];
#pragma unroll
    for (int n = 0; n < 8; n++)
#pragma unroll
        for (int e = 0; e < 4; e++) o[n][e] = 0.0f;
    float m0 = -INFINITY, m1 = -INFINITY, l0 = 0.0f, l1 = 0.0f;

    const int srow = tid >> 2;          // 0..63
    const int sseg = tid & 3;           // 0..3
    const uint32_t* Vthi_u = reinterpret_cast<const uint32_t*>(sVthi);
    const uint32_t* Vtlo_u = reinterpret_cast<const uint32_t*>(sVtlo);

    for (int j0 = 0; j0 < row0 + 128; j0 += 64) {
        __syncthreads();
        // ---- stage K (copy) and V (transpose), all pure byte movement ----
        {
            const size_t rowbase = ((size_t)bh * TSEQ + j0 + srow) * HD;
            const uint4* Kh4 = reinterpret_cast<const uint4*>(g_Kh + rowbase) + sseg * 2;
            const uint4* Kl4 = reinterpret_cast<const uint4*>(g_Kl + rowbase) + sseg * 2;
            uint4* dh = reinterpret_cast<uint4*>(sKhi + srow * FKS + sseg * 8);
            uint4* dl = reinterpret_cast<uint4*>(sKlo + srow * FKS + sseg * 8);
            dh[0] = Kh4[0]; dh[1] = Kh4[1];
            dl[0] = Kl4[0]; dl[1] = Kl4[1];

            uint4 hv[2], lv[2];
            hv[0] = reinterpret_cast<const uint4*>(g_Vh + rowbase + sseg * 16)[0];
            hv[1] = reinterpret_cast<const uint4*>(g_Vh + rowbase + sseg * 16)[1];
            lv[0] = reinterpret_cast<const uint4*>(g_Vl + rowbase + sseg * 16)[0];
            lv[1] = reinterpret_cast<const uint4*>(g_Vl + rowbase + sseg * 16)[1];
            const __nv_bfloat16* hp = reinterpret_cast<const __nv_bfloat16*>(hv);
            const __nv_bfloat16* lp = reinterpret_cast<const __nv_bfloat16*>(lv);
#pragma unroll
            for (int e = 0; e < 16; e++) {
                sVthi[(sseg * 16 + e) * (2*FKS) + srow] = hp[e];
                sVtlo[(sseg * 16 + e) * (2*FKS) + srow] = lp[e];
            }
        }
        __syncthreads();

        // warps entirely above the diagonal skip compute
        if (j0 > row0 + wid * 16 + 15) continue;

        // ---- S = Q K^T ----
        float s[8][4];
#pragma unroll
        for (int n = 0; n < 8; n++)
#pragma unroll
            for (int e = 0; e < 4; e++) s[n][e] = 0.0f;

#pragma unroll
        for (int kc = 0; kc < 4; kc++) {
#pragma unroll
            for (int n = 0; n < 8; n++) {
                const int r = (8 * n + g) * FKS + kc * 8 + q;
                uint32_t bhf[2] = { sKhi[r], sKhi[r + 4] };
                uint32_t blf[2] = { sKlo[r], sKlo[r + 4] };
                mma_bf16(s[n], qh[kc], bhf);
                mma_bf16(s[n], ql[kc], bhf);
                mma_bf16(s[n], qh[kc], blf);
            }
        }

        // ---- causal mask ----
        if (j0 + 63 > row0 + wid * 16) {
#pragma unroll
            for (int n = 0; n < 8; n++) {
                const int col = j0 + 8 * n + 2 * q;
                if (col > r0)     s[n][0] = -1e30f;
                if (col + 1 > r0) s[n][1] = -1e30f;
                if (col > r1)     s[n][2] = -1e30f;
                if (col + 1 > r1) s[n][3] = -1e30f;
            }
        }

        // ---- online softmax ----
        float rmax0 = -1e30f, rmax1 = -1e30f;
#pragma unroll
        for (int n = 0; n < 8; n++) {
            rmax0 = fmaxf(rmax0, fmaxf(s[n][0], s[n][1]));
            rmax1 = fmaxf(rmax1, fmaxf(s[n][2], s[n][3]));
        }
        rmax0 = fmaxf(rmax0, __shfl_xor_sync(0xFFFFFFFFu, rmax0, 1));
        rmax0 = fmaxf(rmax0, __shfl_xor_sync(0xFFFFFFFFu, rmax0, 2));
        rmax1 = fmaxf(rmax1, __shfl_xor_sync(0xFFFFFFFFu, rmax1, 1));
        rmax1 = fmaxf(rmax1, __shfl_xor_sync(0xFFFFFFFFu, rmax1, 2));

        const float mn0 = fmaxf(m0, rmax0);
        const float mn1 = fmaxf(m1, rmax1);
        const float sc0 = fast_exp(m0 - mn0);
        const float sc1 = fast_exp(m1 - mn1);
        m0 = mn0; m1 = mn1;

        float p[8][4];
        float sum0 = 0.0f, sum1 = 0.0f;
#pragma unroll
        for (int n = 0; n < 8; n++) {
            p[n][0] = fast_exp(s[n][0] - mn0);
            p[n][1] = fast_exp(s[n][1] - mn0);
            p[n][2] = fast_exp(s[n][2] - mn1);
            p[n][3] = fast_exp(s[n][3] - mn1);
            sum0 += p[n][0] + p[n][1];
            sum1 += p[n][2] + p[n][3];
        }
        sum0 += __shfl_xor_sync(0xFFFFFFFFu, sum0, 1);
        sum0 += __shfl_xor_sync(0xFFFFFFFFu, sum0, 2);
        sum1 += __shfl_xor_sync(0xFFFFFFFFu, sum1, 1);
        sum1 += __shfl_xor_sync(0xFFFFFFFFu, sum1, 2);
        l0 = l0 * sc0 + sum0;
        l1 = l1 * sc1 + sum1;

#pragma unroll
        for (int n = 0; n < 8; n++) {
            o[n][0] *= sc0; o[n][1] *= sc0;
            o[n][2] *= sc1; o[n][3] *= sc1;
        }

        // ---- O += P V ----
#pragma unroll
        for (int t = 0; t < 4; t++) {
            uint32_t ah[4], al[4];
            split2(p[2*t][0],     p[2*t][1],     ah[0], al[0]);
            split2(p[2*t][2],     p[2*t][3],     ah[1], al[1]);
            split2(p[2*t + 1][0], p[2*t + 1][1], ah[2], al[2]);
            split2(p[2*t + 1][2], p[2*t + 1][3], ah[3], al[3]);
#pragma unroll
            for (int n = 0; n < 8; n++) {
                const int r = (8 * n + g) * FKS + t * 8 + q;
                uint32_t vh[2] = { Vthi_u[r], Vthi_u[r + 4] };
                uint32_t vl[2] = { Vtlo_u[r], Vtlo_u[r + 4] };
                mma_bf16(o[n], ah, vh);
                mma_bf16(o[n], al, vh);
                mma_bf16(o[n], ah, vl);
            }
        }
    }

    // ---- write AO as split bf16 (for out-projection A operand) ----
    const float inv0 = 1.0f / l0;
    const float inv1 = 1.0f / l1;
    const int b = bh >> 4, h = bh & 15;
    uint32_t* AOh32 = reinterpret_cast<uint32_t*>(g_AOh);
    uint32_t* AOl32 = reinterpret_cast<uint32_t*>(g_AOl);
    const size_t base0 = (((size_t)b * TSEQ + r0) * CDIM + h * HD) >> 1;
    const size_t base1 = (((size_t)b * TSEQ + r1) * CDIM + h * HD) >> 1;
#pragma unroll
    for (int n = 0; n < 8; n++) {
        uint32_t hw, lw;
        split2(o[n][0] * inv0, o[n][1] * inv0, hw, lw);
        AOh32[base0 + 4 * n + q] = hw;
        AOl32[base0 + 4 * n + q] = lw;
        split2(o[n][2] * inv1, o[n][3] * inv1, hw, lw);
        AOh32[base1 + 4 * n + q] = hw;
        AOl32[base1 + 4 * n + q] = lw;
    }
}

// ---------------------------------------------------------------------------
extern "C" void kernel_launch(void* const* d_in, const int* in_sizes, int n_in,
                              void* d_out, int out_size)
{
    const float* x     = (const float*)d_in[0];
    const float* in_w  = (const float*)d_in[1];
    const float* in_b  = (const float*)d_in[2];
    const float* out_w = (const float*)d_in[3];
    const float* out_b = (const float*)d_in[4];
    float* out = (float*)d_out;

    cudaFuncSetAttribute(gemm_split<0>, cudaFuncAttributeMaxDynamicSharedMemorySize, GSMEM);
    cudaFuncSetAttribute(gemm_split<1>, cudaFuncAttributeMaxDynamicSharedMemorySize, GSMEM);

    __nv_bfloat16 *pXh, *pXl, *pWih, *pWil, *pWoh, *pWol, *pAOh, *pAOl;
    cudaGetSymbolAddress((void**)&pXh,  g_Xh);  cudaGetSymbolAddress((void**)&pXl,  g_Xl);
    cudaGetSymbolAddress((void**)&pWih, g_Wih); cudaGetSymbolAddress((void**)&pWil, g_Wil);
    cudaGetSymbolAddress((void**)&pWoh, g_Woh); cudaGetSymbolAddress((void**)&pWol, g_Wol);
    cudaGetSymbolAddress((void**)&pAOh, g_AOh); cudaGetSymbolAddress((void**)&pAOl, g_AOl);

    // 0) pre-split x, in_w, out_w into bf16 hi/lo
    split_kernel<<<(M_ROWS*CDIM/4 + 255)/256, 256>>>(x,     pXh,  pXl,  M_ROWS*CDIM/4);
    split_kernel<<<(N_QKV*CDIM/4  + 255)/256, 256>>>(in_w,  pWih, pWil, N_QKV*CDIM/4);
    split_kernel<<<(CDIM*CDIM/4   + 255)/256, 256>>>(out_w, pWoh, pWol, CDIM*CDIM/4);

    // 1) QKV projection -> split Q/K/V (Q pre-scaled)
    gemm_split<0><<<dim3(N_QKV/128, M_ROWS/128), 256, GSMEM>>>(
        pXh, pXl, pWih, pWil, in_b, nullptr, M_ROWS, N_QKV, CDIM);

    // 2) causal flash attention -> split AO
    flash_tc<<<dim3(TSEQ/128, BATCH*NH), 256>>>();

    // 3) output projection -> fp32 out
    gemm_split<1><<<dim3(CDIM/128, M_ROWS/128), 256, GSMEM>>>(
        pAOh, pAOl, pWoh, pWol, out_b, out, M_ROWS, CDIM, CDIM);
}